// round 1
// baseline (speedup 1.0000x reference)
#include <cuda_runtime.h>
#include <math.h>

#define DIMC 512
#define NH 8
#define HD 64
#define NSEQ 4096
#define BATCH 2
#define MROWS (BATCH*NSEQ)   /* 8192 */

// -------- scratch (static device allocations; no cudaMalloc allowed) --------
__device__ float g_Q [MROWS*DIMC];
__device__ float g_K [MROWS*DIMC];
__device__ float g_V [MROWS*DIMC];
__device__ float g_A [MROWS*DIMC];
__device__ float g_CI[MROWS*DIMC];
__device__ float g_CO[MROWS*DIMC];

// ---------------------------------------------------------------------------
// GEMM NT: C[M,512] = A[M,512] @ W[512,512]^T   (torch Linear)
// tile 128x128, ktile 16, 256 threads, 8x8 microtile (stride-16 pattern)
// ---------------------------------------------------------------------------
template<bool ADD>
__global__ __launch_bounds__(256)
void gemm_nt(const float* __restrict__ A, const float* __restrict__ W,
             float* __restrict__ C)
{
    __shared__ float As[16][129];
    __shared__ float Ws[16][129];
    const int tid = threadIdx.x;
    const int tx = tid & 15, ty = tid >> 4;
    const int m0 = blockIdx.x * 128;
    const int n0 = blockIdx.y * 128;

    float acc[8][8];
#pragma unroll
    for (int i = 0; i < 8; i++)
#pragma unroll
        for (int j = 0; j < 8; j++) acc[i][j] = 0.f;

    const int r  = tid >> 2;        // 0..63
    const int kq = (tid & 3) * 4;   // 0,4,8,12

    for (int k0 = 0; k0 < DIMC; k0 += 16) {
#pragma unroll
        for (int p = 0; p < 2; p++) {
            int row = r + p * 64;
            float4 va = *(const float4*)&A[(size_t)(m0 + row) * DIMC + k0 + kq];
            As[kq+0][row] = va.x; As[kq+1][row] = va.y;
            As[kq+2][row] = va.z; As[kq+3][row] = va.w;
            float4 vw = *(const float4*)&W[(size_t)(n0 + row) * DIMC + k0 + kq];
            Ws[kq+0][row] = vw.x; Ws[kq+1][row] = vw.y;
            Ws[kq+2][row] = vw.z; Ws[kq+3][row] = vw.w;
        }
        __syncthreads();
#pragma unroll
        for (int k = 0; k < 16; k++) {
            float a[8], b[8];
#pragma unroll
            for (int i = 0; i < 8; i++) a[i] = As[k][ty + 16*i];
#pragma unroll
            for (int j = 0; j < 8; j++) b[j] = Ws[k][tx + 16*j];
#pragma unroll
            for (int i = 0; i < 8; i++)
#pragma unroll
                for (int j = 0; j < 8; j++)
                    acc[i][j] = fmaf(a[i], b[j], acc[i][j]);
        }
        __syncthreads();
    }

#pragma unroll
    for (int i = 0; i < 8; i++) {
        int m = m0 + ty + 16*i;
#pragma unroll
        for (int j = 0; j < 8; j++) {
            int n = n0 + tx + 16*j;
            if (ADD) C[(size_t)m * DIMC + n] += acc[i][j];
            else     C[(size_t)m * DIMC + n]  = acc[i][j];
        }
    }
}

// ---------------------------------------------------------------------------
// Flash attention, fp32. BM=128 queries/CTA, BN=64 keys/iter, hd=64.
// 256 threads: S micro 8x4 (rows ty+16i, cols tx+16j). Online softmax.
// smem: sQ [64][129] (d-major), sKP union (Ks [64][65] d-major / Ps [64][129]
// key-major), sV [64][64] key-major.
// ---------------------------------------------------------------------------
#define BM 128
#define BN 64
#define SQ_STR 129
#define SK_STR 65
#define SP_STR 129

__global__ __launch_bounds__(256)
void flash_attn(const float* __restrict__ Q, const float* __restrict__ K,
                const float* __restrict__ V, float* __restrict__ Aout)
{
    extern __shared__ float smem[];
    float* sQ  = smem;                 // 64*129 = 8256
    float* sKP = sQ + HD * SQ_STR;     // max(64*65, 64*129) = 8256
    float* sV  = sKP + BN * SP_STR;    // 64*64 = 4096

    const int tid = threadIdx.x;
    const int tx = tid & 15, ty = tid >> 4;
    const int m0 = blockIdx.x * BM;
    const int h  = blockIdx.y;
    const int b  = blockIdx.z;
    const float scale = 0.125f;        // hd^-0.5

    const float* Qb = Q + (size_t)b * NSEQ * DIMC + h * HD;
    const float* Kb = K + (size_t)b * NSEQ * DIMC + h * HD;
    const float* Vb = V + (size_t)b * NSEQ * DIMC + h * HD;

    // load Q tile transposed (d-major), pre-scaled
    {
        int dq = (tid & 15) * 4;
        int r0 = tid >> 4;
#pragma unroll
        for (int p = 0; p < 8; p++) {
            int rr = r0 + p * 16;
            float4 v = *(const float4*)&Qb[(size_t)(m0 + rr) * DIMC + dq];
            sQ[(dq+0)*SQ_STR + rr] = v.x * scale;
            sQ[(dq+1)*SQ_STR + rr] = v.y * scale;
            sQ[(dq+2)*SQ_STR + rr] = v.z * scale;
            sQ[(dq+3)*SQ_STR + rr] = v.w * scale;
        }
    }

    float O[8][4];
    float m_i[8], l_i[8];
#pragma unroll
    for (int i = 0; i < 8; i++) {
        m_i[i] = -1e30f; l_i[i] = 0.f;
#pragma unroll
        for (int j = 0; j < 4; j++) O[i][j] = 0.f;
    }

    for (int n0 = 0; n0 < NSEQ; n0 += BN) {
        __syncthreads();   // prev iter done with sKP/sV (also covers sQ load on iter 0)
        // load K (transposed, d-major) and V (key-major)
        {
            int dq = (tid & 15) * 4;
            int c0 = tid >> 4;
#pragma unroll
            for (int p = 0; p < 4; p++) {
                int c = c0 + p * 16;
                float4 vk = *(const float4*)&Kb[(size_t)(n0 + c) * DIMC + dq];
                sKP[(dq+0)*SK_STR + c] = vk.x;
                sKP[(dq+1)*SK_STR + c] = vk.y;
                sKP[(dq+2)*SK_STR + c] = vk.z;
                sKP[(dq+3)*SK_STR + c] = vk.w;
                float4 vv = *(const float4*)&Vb[(size_t)(n0 + c) * DIMC + dq];
                *(float4*)&sV[c * HD + dq] = vv;
            }
        }
        __syncthreads();

        // S = (Q*scale) @ K^T  micro 8x4
        float S[8][4];
#pragma unroll
        for (int i = 0; i < 8; i++)
#pragma unroll
            for (int j = 0; j < 4; j++) S[i][j] = 0.f;
#pragma unroll 8
        for (int k = 0; k < HD; k++) {
            float a[8], bq[4];
#pragma unroll
            for (int i = 0; i < 8; i++) a[i]  = sQ [k*SQ_STR + ty + 16*i];
#pragma unroll
            for (int j = 0; j < 4; j++) bq[j] = sKP[k*SK_STR + tx + 16*j];
#pragma unroll
            for (int i = 0; i < 8; i++)
#pragma unroll
                for (int j = 0; j < 4; j++)
                    S[i][j] = fmaf(a[i], bq[j], S[i][j]);
        }

        // online softmax (row groups of 16 lanes)
#pragma unroll
        for (int i = 0; i < 8; i++) {
            float mloc = S[i][0];
#pragma unroll
            for (int j = 1; j < 4; j++) mloc = fmaxf(mloc, S[i][j]);
#pragma unroll
            for (int o = 8; o >= 1; o >>= 1)
                mloc = fmaxf(mloc, __shfl_xor_sync(0xffffffffu, mloc, o));
            float mnew  = fmaxf(m_i[i], mloc);
            float alpha = __expf(m_i[i] - mnew);
            float s = 0.f;
#pragma unroll
            for (int j = 0; j < 4; j++) {
                float p = __expf(S[i][j] - mnew);
                S[i][j] = p; s += p;
            }
#pragma unroll
            for (int o = 8; o >= 1; o >>= 1)
                s += __shfl_xor_sync(0xffffffffu, s, o);
            l_i[i] = l_i[i] * alpha + s;
            m_i[i] = mnew;
#pragma unroll
            for (int j = 0; j < 4; j++) O[i][j] *= alpha;
        }

        __syncthreads();   // everyone done reading Ks before Ps overwrites it
#pragma unroll
        for (int i = 0; i < 8; i++)
#pragma unroll
            for (int j = 0; j < 4; j++)
                sKP[(tx + 16*j)*SP_STR + (ty + 16*i)] = S[i][j];
        __syncthreads();

        // O += P @ V
#pragma unroll 8
        for (int c = 0; c < BN; c++) {
            float a[8], bv[4];
#pragma unroll
            for (int i = 0; i < 8; i++) a[i]  = sKP[c*SP_STR + ty + 16*i];
#pragma unroll
            for (int j = 0; j < 4; j++) bv[j] = sV [c*HD     + tx + 16*j];
#pragma unroll
            for (int i = 0; i < 8; i++)
#pragma unroll
                for (int j = 0; j < 4; j++)
                    O[i][j] = fmaf(a[i], bv[j], O[i][j]);
        }
    }

    // normalize + write
#pragma unroll
    for (int i = 0; i < 8; i++) {
        float inv = 1.f / l_i[i];
        int row = m0 + ty + 16*i;
#pragma unroll
        for (int j = 0; j < 4; j++) {
            int d = tx + 16*j;
            Aout[((size_t)b * NSEQ + row) * DIMC + h * HD + d] = O[i][j] * inv;
        }
    }
}

// ---------------------------------------------------------------------------
// depthwise conv over N (k=3, pad=1, cross-correlation) + bias
// ---------------------------------------------------------------------------
__global__ __launch_bounds__(256)
void dwconv(const float* __restrict__ CI, const float* __restrict__ kern,
            const float* __restrict__ bias, float* __restrict__ CO)
{
    int idx = blockIdx.x * blockDim.x + threadIdx.x;
    if (idx >= MROWS * DIMC) return;
    int c   = idx & (DIMC - 1);
    int row = idx >> 9;            // b*N + n
    int n   = row & (NSEQ - 1);
    float k0 = kern[c*3+0], k1 = kern[c*3+1], k2 = kern[c*3+2];
    float acc = bias[c] + k1 * CI[idx];
    if (n > 0)        acc += k0 * CI[idx - DIMC];
    if (n < NSEQ - 1) acc += k2 * CI[idx + DIMC];
    CO[idx] = acc;
}

// ---------------------------------------------------------------------------
extern "C" void kernel_launch(void* const* d_in, const int* in_sizes, int n_in,
                              void* d_out, int out_size)
{
    const float* x     = (const float*)d_in[0];
    const float* Wq    = (const float*)d_in[1];
    const float* Wk    = (const float*)d_in[2];
    const float* Wv    = (const float*)d_in[3];
    const float* Wattn = (const float*)d_in[4];
    const float* Wconv = (const float*)d_in[5];
    const float* dwk   = (const float*)d_in[6];
    const float* dwb   = (const float*)d_in[7];
    const float* Wcout = (const float*)d_in[8];
    float* out = (float*)d_out;

    float *Qp, *Kp, *Vp, *Ap, *CIp, *COp;
    cudaGetSymbolAddress((void**)&Qp,  g_Q);
    cudaGetSymbolAddress((void**)&Kp,  g_K);
    cudaGetSymbolAddress((void**)&Vp,  g_V);
    cudaGetSymbolAddress((void**)&Ap,  g_A);
    cudaGetSymbolAddress((void**)&CIp, g_CI);
    cudaGetSymbolAddress((void**)&COp, g_CO);

    const int flash_smem = (HD*SQ_STR + BN*SP_STR + BN*HD) * (int)sizeof(float); // 82432
    cudaFuncSetAttribute(flash_attn,
                         cudaFuncAttributeMaxDynamicSharedMemorySize, flash_smem);

    dim3 gg(MROWS / 128, DIMC / 128);   // 64 x 4
    dim3 bb(256);

    gemm_nt<false><<<gg, bb>>>(x, Wq,    Qp);
    gemm_nt<false><<<gg, bb>>>(x, Wk,    Kp);
    gemm_nt<false><<<gg, bb>>>(x, Wv,    Vp);
    gemm_nt<false><<<gg, bb>>>(x, Wconv, CIp);

    flash_attn<<<dim3(NSEQ / BM, NH, BATCH), 256, flash_smem>>>(Qp, Kp, Vp, Ap);

    gemm_nt<false><<<gg, bb>>>(Ap, Wattn, out);

    dwconv<<<(MROWS * DIMC) / 256, 256>>>(CIp, dwk, dwb, COp);

    gemm_nt<true><<<gg, bb>>>(COp, Wcout, out);
}